// round 2
// baseline (speedup 1.0000x reference)
#include <cuda_runtime.h>
#include <cuda_bf16.h>

#define Bn  4
#define Tn  2048
#define DMn 768
#define Hn  12
#define DHn 64

// Scratch (device globals — no allocation allowed in kernel_launch)
__device__ __align__(16) float g_q[Bn*Hn*Tn*DHn];
__device__ __align__(16) float g_k[Bn*Hn*Tn*DHn];
__device__ __align__(16) float g_v[Bn*Hn*Tn*DHn];
__device__ __align__(16) float g_o[Bn*Tn*DMn];

// ---------------------------------------------------------------------------
// Kernel A: QKV GEMM (C[m,n] = sum_k x[m,k] * W[n,k]) with fused RoPE +
// transpose-to-[B,H,T,DH] epilogue. 64x64 tile, BK=16, 256 thr, 4x4 micro.
// blockIdx.x = mat*12 + ntile (mat: 0=Q,1=K,2=V), blockIdx.y = mtile.
// ---------------------------------------------------------------------------
__global__ __launch_bounds__(256) void qkv_gemm(
    const float* __restrict__ x,
    const float* __restrict__ wq, const float* __restrict__ wk,
    const float* __restrict__ wv,
    const float* __restrict__ cosb, const float* __restrict__ sinb)
{
    __shared__ float Xs[16][65];
    __shared__ float Ws[16][65];

    const int mat = blockIdx.x / 12;
    const int nt  = blockIdx.x % 12;
    const int mt  = blockIdx.y;
    const float* W = (mat == 0) ? wq : ((mat == 1) ? wk : wv);
    const int m0 = mt * 64, n0 = nt * 64;
    const int tid = threadIdx.x;
    const int lr = tid >> 2, lc = tid & 3;   // load mapping: 64 rows x 4 float4
    const int ty = tid >> 4, tx = tid & 15;  // compute mapping: 16x16 threads

    float acc[4][4];
    #pragma unroll
    for (int i = 0; i < 4; i++)
        #pragma unroll
        for (int j = 0; j < 4; j++) acc[i][j] = 0.f;

    const float* xrow = x + (m0 + lr) * DMn + lc * 4;
    const float* wrow = W + (n0 + lr) * DMn + lc * 4;

    for (int k0 = 0; k0 < DMn; k0 += 16) {
        float4 xa = *(const float4*)(xrow + k0);
        float4 wa = *(const float4*)(wrow + k0);
        Xs[lc*4+0][lr] = xa.x; Xs[lc*4+1][lr] = xa.y;
        Xs[lc*4+2][lr] = xa.z; Xs[lc*4+3][lr] = xa.w;
        Ws[lc*4+0][lr] = wa.x; Ws[lc*4+1][lr] = wa.y;
        Ws[lc*4+2][lr] = wa.z; Ws[lc*4+3][lr] = wa.w;
        __syncthreads();
        #pragma unroll
        for (int kk = 0; kk < 16; kk++) {
            float a0 = Xs[kk][ty*4+0], a1 = Xs[kk][ty*4+1];
            float a2 = Xs[kk][ty*4+2], a3 = Xs[kk][ty*4+3];
            float b0 = Ws[kk][tx*4+0], b1 = Ws[kk][tx*4+1];
            float b2 = Ws[kk][tx*4+2], b3 = Ws[kk][tx*4+3];
            acc[0][0] += a0*b0; acc[0][1] += a0*b1; acc[0][2] += a0*b2; acc[0][3] += a0*b3;
            acc[1][0] += a1*b0; acc[1][1] += a1*b1; acc[1][2] += a1*b2; acc[1][3] += a1*b3;
            acc[2][0] += a2*b0; acc[2][1] += a2*b1; acc[2][2] += a2*b2; acc[2][3] += a2*b3;
            acc[3][0] += a3*b0; acc[3][1] += a3*b1; acc[3][2] += a3*b2; acc[3][3] += a3*b3;
        }
        __syncthreads();
    }

    // Epilogue: n-tile == head (DH==64==BN). Apply RoPE for Q/K, write
    // [B,H,T,DH] layout.
    float* dst = (mat == 0) ? g_q : ((mat == 1) ? g_k : g_v);
    #pragma unroll
    for (int i = 0; i < 4; i++) {
        int mm = m0 + ty * 4 + i;
        int b  = mm / Tn, t = mm % Tn;
        int base = ((b * Hn + nt) * Tn + t) * DHn + tx * 4;
        if (mat < 2) {
            int pi = tx * 2;  // rope pair index (f = tx*4 .. tx*4+3 -> pairs pi, pi+1)
            float c0 = cosb[t*32 + pi],   s0 = sinb[t*32 + pi];
            float c1 = cosb[t*32 + pi+1], s1 = sinb[t*32 + pi+1];
            float4 r;
            r.x = acc[i][0]*c0 - acc[i][1]*s0;
            r.y = acc[i][0]*s0 + acc[i][1]*c0;
            r.z = acc[i][2]*c1 - acc[i][3]*s1;
            r.w = acc[i][2]*s1 + acc[i][3]*c1;
            *(float4*)(dst + base) = r;
        } else {
            *(float4*)(dst + base) = make_float4(acc[i][0], acc[i][1], acc[i][2], acc[i][3]);
        }
    }
}

// ---------------------------------------------------------------------------
// Kernel B: causal flash attention, fp32. 1 query per thread, 128 q/block,
// 32-key tiles staged in smem (broadcast LDS reads), online softmax.
// grid: (16 qtiles, 48 bh). qtiles processed in reverse for load balance.
// ---------------------------------------------------------------------------
__global__ __launch_bounds__(128) void attn_kernel()
{
    __shared__ __align__(16) float Ks[32 * 64];
    __shared__ __align__(16) float Vs[32 * 64];

    const int qt  = (int)gridDim.x - 1 - (int)blockIdx.x;
    const int bh  = blockIdx.y;
    const int tid = threadIdx.x;
    const int t   = qt * 128 + tid;

    const float* qp = g_q + (bh * Tn + t) * DHn;
    float4 qv[16];
    #pragma unroll
    for (int i = 0; i < 16; i++) qv[i] = *(const float4*)(qp + i * 4);

    float4 av[16];
    #pragma unroll
    for (int i = 0; i < 16; i++) av[i] = make_float4(0.f, 0.f, 0.f, 0.f);

    float mx = -1e30f, l = 0.f;
    const float4* kb = (const float4*)(g_k + bh * Tn * DHn);
    const float4* vb = (const float4*)(g_v + bh * Tn * DHn);
    const int ktmax = 4 * qt + 3;
    float s[32];

    for (int kt = 0; kt <= ktmax; kt++) {
        // stage K/V tile: 32 rows x 16 float4 = 512 float4 each
        #pragma unroll
        for (int i = 0; i < 4; i++) {
            ((float4*)Ks)[tid + i * 128] = kb[kt * 512 + tid + i * 128];
            ((float4*)Vs)[tid + i * 128] = vb[kt * 512 + tid + i * 128];
        }
        __syncthreads();

        // phase 1: scores + tile max
        float mtile = -1e30f;
        #pragma unroll 4
        for (int j = 0; j < 32; j++) {
            const float4* kr = (const float4*)(Ks + j * 64);
            float acc = 0.f;
            #pragma unroll
            for (int d = 0; d < 16; d++) {
                float4 k4 = kr[d];
                acc += qv[d].x * k4.x + qv[d].y * k4.y
                     + qv[d].z * k4.z + qv[d].w * k4.w;
            }
            acc *= 0.125f;                       // DH^-0.5
            if (kt * 32 + j > t) acc = -1e30f;   // causal mask
            s[j] = acc;
            mtile = fmaxf(mtile, acc);
        }

        // online softmax rescale
        float newm = fmaxf(mx, mtile);
        float corr = __expf(mx - newm);
        mx = newm;
        l *= corr;
        #pragma unroll
        for (int d = 0; d < 16; d++) {
            av[d].x *= corr; av[d].y *= corr; av[d].z *= corr; av[d].w *= corr;
        }

        // phase 2: P @ V
        #pragma unroll 4
        for (int j = 0; j < 32; j++) {
            float p = __expf(s[j] - mx);
            l += p;
            const float4* vr = (const float4*)(Vs + j * 64);
            #pragma unroll
            for (int d = 0; d < 16; d++) {
                float4 v4 = vr[d];
                av[d].x += p * v4.x; av[d].y += p * v4.y;
                av[d].z += p * v4.z; av[d].w += p * v4.w;
            }
        }
        __syncthreads();
    }

    float inv = 1.f / l;
    int b = bh / Hn, h = bh % Hn;
    float* op = g_o + (b * Tn + t) * DMn + h * DHn;
    #pragma unroll
    for (int d = 0; d < 16; d++) {
        *(float4*)(op + d * 4) =
            make_float4(av[d].x * inv, av[d].y * inv, av[d].z * inv, av[d].w * inv);
    }
}

// ---------------------------------------------------------------------------
// Kernel C: output projection out[m,n] = sum_k g_o[m,k] * wo[n,k]
// ---------------------------------------------------------------------------
__global__ __launch_bounds__(256) void proj_gemm(
    const float* __restrict__ wo, float* __restrict__ out)
{
    __shared__ float Xs[16][65];
    __shared__ float Ws[16][65];

    const int nt = blockIdx.x;
    const int mt = blockIdx.y;
    const int m0 = mt * 64, n0 = nt * 64;
    const int tid = threadIdx.x;
    const int lr = tid >> 2, lc = tid & 3;
    const int ty = tid >> 4, tx = tid & 15;

    float acc[4][4];
    #pragma unroll
    for (int i = 0; i < 4; i++)
        #pragma unroll
        for (int j = 0; j < 4; j++) acc[i][j] = 0.f;

    const float* xrow = g_o + (m0 + lr) * DMn + lc * 4;
    const float* wrow = wo  + (n0 + lr) * DMn + lc * 4;

    for (int k0 = 0; k0 < DMn; k0 += 16) {
        float4 xa = *(const float4*)(xrow + k0);
        float4 wa = *(const float4*)(wrow + k0);
        Xs[lc*4+0][lr] = xa.x; Xs[lc*4+1][lr] = xa.y;
        Xs[lc*4+2][lr] = xa.z; Xs[lc*4+3][lr] = xa.w;
        Ws[lc*4+0][lr] = wa.x; Ws[lc*4+1][lr] = wa.y;
        Ws[lc*4+2][lr] = wa.z; Ws[lc*4+3][lr] = wa.w;
        __syncthreads();
        #pragma unroll
        for (int kk = 0; kk < 16; kk++) {
            float a0 = Xs[kk][ty*4+0], a1 = Xs[kk][ty*4+1];
            float a2 = Xs[kk][ty*4+2], a3 = Xs[kk][ty*4+3];
            float b0 = Ws[kk][tx*4+0], b1 = Ws[kk][tx*4+1];
            float b2 = Ws[kk][tx*4+2], b3 = Ws[kk][tx*4+3];
            acc[0][0] += a0*b0; acc[0][1] += a0*b1; acc[0][2] += a0*b2; acc[0][3] += a0*b3;
            acc[1][0] += a1*b0; acc[1][1] += a1*b1; acc[1][2] += a1*b2; acc[1][3] += a1*b3;
            acc[2][0] += a2*b0; acc[2][1] += a2*b1; acc[2][2] += a2*b2; acc[2][3] += a2*b3;
            acc[3][0] += a3*b0; acc[3][1] += a3*b1; acc[3][2] += a3*b2; acc[3][3] += a3*b3;
        }
        __syncthreads();
    }

    #pragma unroll
    for (int i = 0; i < 4; i++) {
        int mm = m0 + ty * 4 + i;
        *(float4*)(out + mm * DMn + n0 + tx * 4) =
            make_float4(acc[i][0], acc[i][1], acc[i][2], acc[i][3]);
    }
}

// ---------------------------------------------------------------------------
extern "C" void kernel_launch(void* const* d_in, const int* in_sizes, int n_in,
                              void* d_out, int out_size)
{
    const float* x    = (const float*)d_in[0];
    const float* cosb = (const float*)d_in[1];
    const float* sinb = (const float*)d_in[2];
    const float* wq   = (const float*)d_in[3];
    const float* wk   = (const float*)d_in[4];
    const float* wv   = (const float*)d_in[5];
    const float* wo   = (const float*)d_in[6];
    float* out = (float*)d_out;

    dim3 gA(36, 128);   // 3 mats x 12 ntiles, 128 mtiles
    qkv_gemm<<<gA, 256>>>(x, wq, wk, wv, cosb, sinb);

    dim3 gB(16, 48);    // 16 qtiles, B*H
    attn_kernel<<<gB, 128>>>();

    dim3 gC(12, 128);
    proj_gemm<<<gC, 256>>>(wo, out);
}